// round 8
// baseline (speedup 1.0000x reference)
#include <cuda_runtime.h>
#include <cuda_bf16.h>
#include <math.h>
#include <stdint.h>

// Problem constants
#define BQ 32
#define WQ 64
#define MQ 16
#define LQ 8192
#define NBQ 32
#define KSPL 16

// ---------------- scratch (device globals: allocation-free rule) ----------
__device__ __align__(16) uint32_t g_hpkA[BQ * WQ * LQ];   // packed bf16 hi|lo h (64 MB)
__device__ __align__(16) uint32_t g_hpkB[BQ * WQ * LQ];   // 64 MB
__device__ __align__(16) uint32_t g_Tpk[NBQ * LQ];        // packed basis [n][l] (1 MB)
__device__ __align__(16) uint32_t g_Bhi[NBQ * LQ];        // (T_hi,T_hi) pairs [n][l] (1 MB)
__device__ __align__(16) uint32_t g_Blo[NBQ * LQ];        // (T_lo,T_lo) pairs [n][l] (1 MB)
__device__ float    g_Fpart[BQ * NBQ * KSPL * WQ];        // DFT partials [b][n][p][c] (8 MB)
__device__ uint32_t g_coefpk[BQ * WQ * NBQ];              // packed coef (1 MB)
__device__ uint32_t g_convpk[4 * WQ * WQ];                // packed conv weights

__device__ __forceinline__ float gelu_exact(float v) {
    return 0.5f * v * (1.0f + erff(v * 0.70710678118654752440f));
}

// bf16 hi/lo packing: low 16 bits = hi part, high 16 bits = lo part
__device__ __forceinline__ uint32_t pk(float v) {
    __nv_bfloat16 h = __float2bfloat16(v);
    __nv_bfloat16 l = __float2bfloat16(v - __bfloat162float(h));
    return (uint32_t)__bfloat16_as_ushort(h) | ((uint32_t)__bfloat16_as_ushort(l) << 16);
}
__device__ __forceinline__ float upk(uint32_t u) {
    return __bfloat162float(__ushort_as_bfloat16((unsigned short)(u & 0xFFFFu)))
         + __bfloat162float(__ushort_as_bfloat16((unsigned short)(u >> 16)));
}

// warp-level bf16 MMA (baseline PTX, sm_80+; tensor pipe)
__device__ __forceinline__ void mma16816(float* d, const uint32_t* a,
                                         uint32_t b0, uint32_t b1) {
    asm volatile(
        "mma.sync.aligned.m16n8k16.row.col.f32.bf16.bf16.f32 "
        "{%0,%1,%2,%3}, {%4,%5,%6,%7}, {%8,%9}, {%0,%1,%2,%3};"
        : "+f"(d[0]), "+f"(d[1]), "+f"(d[2]), "+f"(d[3])
        : "r"(a[0]), "r"(a[1]), "r"(a[2]), "r"(a[3]), "r"(b0), "r"(b1));
}

// fused kernel smem layout (bytes)
#define AS_B 404
#define OFF_A   0
#define OFF_BHI 51712
#define OFF_BLO 77568
#define FUSED_SMEM 103424

// fwd reduction smem: Dw[8 warps][32 n][stride 68 c]  (conflict-free: bank=8q+r)
#define DW_STRIDE 68
#define FWD_SMEM (8 * 32 * DW_STRIDE * 4)

// ---------------------------------------------------------------------------
// Basis tables: packed pairs for fused A-tiles, (hi,hi)/(lo,lo) for fwd B.
// ---------------------------------------------------------------------------
__global__ void build_table_kernel() {
    int idx = blockIdx.x * blockDim.x + threadIdx.x;  // 131072
    int k = idx >> 13;
    int l = idx & (LQ - 1);
    int m = (k * l) & (LQ - 1);
    float ang = (float)m * (6.283185307179586476925f / (float)LQ);
    float s, c;
    sincosf(ang, &s, &c);
    uint32_t cp = pk(c), sp = pk(s);
    g_Tpk[(2 * k) * LQ + l]     = cp;
    g_Tpk[(2 * k + 1) * LQ + l] = sp;
    uint32_t ch = cp & 0xFFFFu, cl = cp >> 16;
    uint32_t sh = sp & 0xFFFFu, sl = sp >> 16;
    g_Bhi[(2 * k) * LQ + l]     = ch | (ch << 16);
    g_Blo[(2 * k) * LQ + l]     = cl | (cl << 16);
    g_Bhi[(2 * k + 1) * LQ + l] = sh | (sh << 16);
    g_Blo[(2 * k + 1) * LQ + l] = sl | (sl << 16);
}

__global__ void convprep_kernel(const float* __restrict__ cw) {
    int idx = blockIdx.x * 256 + threadIdx.x;   // 16384
    g_convpk[idx] = pk(cw[idx]);
}

// ---------------------------------------------------------------------------
// Lifting -> packed h
// ---------------------------------------------------------------------------
__global__ void lift_kernel(const float* __restrict__ x,
                            const float* __restrict__ Pw,
                            const float* __restrict__ Pb,
                            uint32_t* __restrict__ hpk) {
    int idx = blockIdx.x * 256 + threadIdx.x;
    int l = idx & (LQ - 1);
    int w = (idx >> 13) & 63;
    int b = idx >> 19;
    float x0 = x[(b * 2 + 0) * LQ + l];
    float x1 = x[(b * 2 + 1) * LQ + l];
    hpk[idx] = pk(Pw[2 * w] * x0 + Pw[2 * w + 1] * x1 + Pb[w]);
}

// ---------------------------------------------------------------------------
// Forward DFT via mma.sync bf16-split:
//   Fpart[b,ks][c=64, n=32] = sum over 512-l slice of h[c,l] * T[l,n]
// A k-slots (2l,2l+1) = packed h word l (hi,lo) -- zero repack.
// B pass-hi: (Th,Th) word; pass-lo: (Tl,Tl). Sum = (hh+hl)(Th+Tl) = h*T.
// Grid (B, KSPL); 8 warps, warp w owns ksteps [w*8, w*8+8) (K-split in CTA),
// all 4x4 m16n8 tiles (64 fp32 accs). Direct LDG fragments (B tables are
// L2-resident). Epilogue: conflict-free smem reduce across warps,
// coalesced partial store.
// ---------------------------------------------------------------------------
__global__ void __launch_bounds__(256) fwd_mma_kernel(const uint32_t* __restrict__ hpk) {
    extern __shared__ __align__(16) float Dw[];
    int b = blockIdx.x;
    int ks = blockIdx.y;
    int t = threadIdx.x;
    int w = t >> 5;
    int lane = t & 31;
    int r = lane >> 2;
    int q = lane & 3;

    float d[4][4][4];
#pragma unroll
    for (int mi = 0; mi < 4; mi++)
#pragma unroll
        for (int ni = 0; ni < 4; ni++)
#pragma unroll
            for (int e = 0; e < 4; e++) d[mi][ni][e] = 0.f;

    const uint32_t* hb = hpk + (size_t)b * 64 * LQ;

#pragma unroll 2
    for (int i = 0; i < 8; i++) {
        int lw = ks * 512 + (w * 8 + i) * 8;     // word (=l) base of this kstep
        uint32_t a[4][4];
#pragma unroll
        for (int mi = 0; mi < 4; mi++) {
            const uint32_t* ap = hb + (size_t)(mi * 16 + r) * LQ + lw;
            a[mi][0] = ap[q];
            a[mi][1] = ap[8 * LQ + q];
            a[mi][2] = ap[q + 4];
            a[mi][3] = ap[8 * LQ + q + 4];
        }
#pragma unroll
        for (int pass = 0; pass < 2; pass++) {
            const uint32_t* Bt = pass ? g_Blo : g_Bhi;
#pragma unroll
            for (int ni = 0; ni < 4; ni++) {
                const uint32_t* bp = Bt + (size_t)(ni * 8 + r) * LQ + lw;
                uint32_t b0 = bp[q];
                uint32_t b1 = bp[q + 4];
#pragma unroll
                for (int mi = 0; mi < 4; mi++)
                    mma16816(d[mi][ni], a[mi], b0, b1);
            }
        }
    }

    // ---- per-warp partial -> smem (Dw[w][n][c], stride 68: banks 8q+r) ---
    float* dw = Dw + w * (32 * DW_STRIDE);
#pragma unroll
    for (int mi = 0; mi < 4; mi++)
#pragma unroll
        for (int ni = 0; ni < 4; ni++) {
            int c = mi * 16 + r;
            int n = ni * 8 + 2 * q;
            dw[n * DW_STRIDE + c]           = d[mi][ni][0];
            dw[(n + 1) * DW_STRIDE + c]     = d[mi][ni][1];
            dw[n * DW_STRIDE + c + 8]       = d[mi][ni][2];
            dw[(n + 1) * DW_STRIDE + c + 8] = d[mi][ni][3];
        }
    __syncthreads();

    // ---- reduce 8 warps, coalesced store --------------------------------
#pragma unroll
    for (int j = 0; j < 8; j++) {
        int idx = t + 256 * j;          // 2048 = 32 n x 64 c
        int n = idx >> 6;
        int c = idx & 63;
        float s = 0.f;
#pragma unroll
        for (int ww = 0; ww < 8; ww++)
            s += Dw[ww * (32 * DW_STRIDE) + n * DW_STRIDE + c];
        g_Fpart[((size_t)(b * NBQ + n) * KSPL + ks) * 64 + c] = s;
    }
}

// ---------------------------------------------------------------------------
// Mode mixing -> packed coefficients. (unchanged from R7)
// ---------------------------------------------------------------------------
__global__ void __launch_bounds__(256) mode_mix_kernel(const float* __restrict__ kwr,
                                                       const float* __restrict__ kwi, int ib) {
    int k = blockIdx.x;
    int bg = blockIdx.y;
    int t = threadIdx.x;
    int o = t & 63;
    int bb = t >> 6;
    int b = bg * 4 + bb;
    __shared__ float wrS[64 * 65], wiS[64 * 65];
    __shared__ float HrS[4][64], HsS[4][64];

    const float* wrG = kwr + ((size_t)ib * 16 + k) * 4096;
    const float* wiG = kwi + ((size_t)ib * 16 + k) * 4096;
#pragma unroll
    for (int j = 0; j < 16; j++) {
        int idx = t + 256 * j;
        int row = idx >> 6, col = idx & 63;
        wrS[row * 65 + col] = wrG[idx];
        wiS[row * 65 + col] = wiG[idx];
    }

    float hr = 0.f, hs = 0.f;
    const float* fr = g_Fpart + (size_t)(b * NBQ + 2 * k) * KSPL * 64;
    const float* fs = g_Fpart + (size_t)(b * NBQ + 2 * k + 1) * KSPL * 64;
#pragma unroll
    for (int p = 0; p < KSPL; p++) {
        hr += fr[p * 64 + o];
        hs += fs[p * 64 + o];
    }
    HrS[bb][o] = hr;
    HsS[bb][o] = hs;
    __syncthreads();

    float ar = 0.f, ai = 0.f;
#pragma unroll 8
    for (int i = 0; i < 64; i++) {
        float xr = HrS[bb][i];
        float xi = -HsS[bb][i];
        float wrv = wrS[o * 65 + i];
        float wiv = wiS[o * 65 + i];
        ar += wrv * xr - wiv * xi;
        ai += wrv * xi + wiv * xr;
    }
    const float invL = 1.0f / (float)LQ;
    float cC, cS;
    if (k == 0) { cC = ar * invL;        cS = 0.f; }
    else        { cC = 2.f * ar * invL;  cS = -2.f * ai * invL; }
    g_coefpk[(b * 64 + o) * NBQ + 2 * k]     = pk(cC);
    g_coefpk[(b * 64 + o) * NBQ + 2 * k + 1] = pk(cS);
}

// ---------------------------------------------------------------------------
// Fused block via mma.sync bf16-split. (unchanged from R7 — validated)
// ---------------------------------------------------------------------------
template <bool LAST>
__global__ void __launch_bounds__(256) fused_mma_kernel(
    const uint32_t* __restrict__ hin, uint32_t* __restrict__ hout,
    const float* __restrict__ cb, int ib,
    const float* __restrict__ Qw, const float* __restrict__ Qb,
    float* __restrict__ outp) {
    extern __shared__ __align__(16) char smem[];
    char* Asm = smem + OFF_A;
    int b = blockIdx.y;
    int t = threadIdx.x;
    int wid = t >> 5;
    int lane = t & 31;
    int l0 = blockIdx.x * 128;

    const uint32_t* hsrc = hin + (size_t)b * 64 * LQ;
#pragma unroll
    for (int j = 0; j < 48; j++) {
        int id = t + 256 * j;            // 12288 = 96 ch x 128 l
        int c = id >> 7;
        int l = id & 127;
        const uint32_t* src = (c < 32) ? (g_Tpk + (size_t)c * LQ)
                                       : (hsrc + (size_t)(c - 32) * LQ);
        uint32_t u = src[l0 + l];
        *(uint32_t*)(Asm + l * AS_B + c * 4) = u;
    }
#pragma unroll
    for (int j = 0; j < 24; j++) {
        int id = t + 256 * j;            // 6144 = 64 o x 96 c
        int o = id / 96;
        int c = id - o * 96;
        uint32_t u = (c < 32) ? g_coefpk[((size_t)b * 64 + o) * NBQ + c]
                              : g_convpk[ib * 4096 + o * 64 + (c - 32)];
        uint32_t wh = u & 0xFFFFu;
        uint32_t wl = u >> 16;
        *(uint32_t*)(smem + OFF_BHI + o * AS_B + c * 4) = wh | (wh << 16);
        *(uint32_t*)(smem + OFF_BLO + o * AS_B + c * 4) = wl | (wl << 16);
    }
    __syncthreads();

    int wm = wid >> 1;
    int wn = wid & 1;
    int r = lane >> 2;
    int q = lane & 3;
    float d[2][4][4];
#pragma unroll
    for (int mi = 0; mi < 2; mi++)
#pragma unroll
        for (int ni = 0; ni < 4; ni++)
#pragma unroll
            for (int e = 0; e < 4; e++) d[mi][ni][e] = 0.f;

#pragma unroll
    for (int ks = 0; ks < 12; ks++) {
        int kb = (ks * 16 + q * 2) * 2;
        uint32_t a[2][4];
#pragma unroll
        for (int mi = 0; mi < 2; mi++) {
            const char* arow = Asm + (wm * 32 + mi * 16 + r) * AS_B + kb;
            a[mi][0] = *(const uint32_t*)(arow);
            a[mi][1] = *(const uint32_t*)(arow + 8 * AS_B);
            a[mi][2] = *(const uint32_t*)(arow + 16);
            a[mi][3] = *(const uint32_t*)(arow + 8 * AS_B + 16);
        }
#pragma unroll
        for (int pass = 0; pass < 2; pass++) {
            const char* Bp = smem + (pass ? OFF_BLO : OFF_BHI);
#pragma unroll
            for (int ni = 0; ni < 4; ni++) {
                const char* brow = Bp + (wn * 32 + ni * 8 + r) * AS_B + kb;
                uint32_t b0 = *(const uint32_t*)(brow);
                uint32_t b1 = *(const uint32_t*)(brow + 16);
                mma16816(d[0][ni], a[0], b0, b1);
                mma16816(d[1][ni], a[1], b0, b1);
            }
        }
    }

    __syncthreads();
    float* D = (float*)Asm;              // D[o][129]
#pragma unroll
    for (int mi = 0; mi < 2; mi++)
#pragma unroll
        for (int ni = 0; ni < 4; ni++) {
            int l = wm * 32 + mi * 16 + r;
            int o = wn * 32 + ni * 8 + q * 2;
            D[o * 129 + l]           = d[mi][ni][0];
            D[(o + 1) * 129 + l]     = d[mi][ni][1];
            D[o * 129 + l + 8]       = d[mi][ni][2];
            D[(o + 1) * 129 + l + 8] = d[mi][ni][3];
        }
    __syncthreads();

    if (!LAST) {
#pragma unroll
        for (int j = 0; j < 32; j++) {
            int idx = t + 256 * j;
            int o = idx >> 7;
            int l = idx & 127;
            float v = D[o * 129 + l] + __ldg(&cb[ib * 64 + o]);
            hout[((size_t)b * 64 + o) * LQ + l0 + l] = pk(gelu_exact(v));
        }
    } else {
        float* partS = (float*)(smem + OFF_BHI);
        int l = t & 127;
        int ob = t >> 7;
        float s = 0.f;
#pragma unroll
        for (int j = 0; j < 32; j++) {
            int o = ob + 2 * j;
            float v = D[o * 129 + l] + __ldg(&cb[ib * 64 + o]);
            s += __ldg(&Qw[o]) * gelu_exact(v);
        }
        partS[ob * 128 + l] = s;
        __syncthreads();
        if (t < 128)
            outp[(size_t)b * LQ + l0 + t] = partS[t] + partS[128 + t] + __ldg(&Qb[0]);
    }
}

// ---------------------------------------------------------------------------
extern "C" void kernel_launch(void* const* d_in, const int* in_sizes, int n_in,
                              void* d_out, int out_size) {
    const float* x   = (const float*)d_in[0];
    const float* Pw  = (const float*)d_in[1];
    const float* Pb  = (const float*)d_in[2];
    const float* kwr = (const float*)d_in[3];
    const float* kwi = (const float*)d_in[4];
    const float* cw  = (const float*)d_in[5];
    const float* cb  = (const float*)d_in[6];
    const float* Qw  = (const float*)d_in[7];
    const float* Qb  = (const float*)d_in[8];
    float* out = (float*)d_out;

    uint32_t *hA = nullptr, *hB = nullptr;
    cudaGetSymbolAddress((void**)&hA, g_hpkA);
    cudaGetSymbolAddress((void**)&hB, g_hpkB);

    cudaFuncSetAttribute(fused_mma_kernel<false>,
                         cudaFuncAttributeMaxDynamicSharedMemorySize, FUSED_SMEM);
    cudaFuncSetAttribute(fused_mma_kernel<true>,
                         cudaFuncAttributeMaxDynamicSharedMemorySize, FUSED_SMEM);
    cudaFuncSetAttribute(fwd_mma_kernel,
                         cudaFuncAttributeMaxDynamicSharedMemorySize, FWD_SMEM);

    build_table_kernel<<<(LQ * MQ) / 256, 256>>>();
    convprep_kernel<<<64, 256>>>(cw);
    lift_kernel<<<(BQ * WQ * LQ) / 256, 256>>>(x, Pw, Pb, hA);

    uint32_t* cur = hA;
    uint32_t* nxt = hB;
    for (int ib = 0; ib < 4; ib++) {
        fwd_mma_kernel<<<dim3(BQ, KSPL), 256, FWD_SMEM>>>(cur);
        mode_mix_kernel<<<dim3(16, 8), 256>>>(kwr, kwi, ib);
        if (ib < 3) {
            fused_mma_kernel<false><<<dim3(LQ / 128, BQ), 256, FUSED_SMEM>>>(
                cur, nxt, cb, ib, Qw, Qb, out);
        } else {
            fused_mma_kernel<true><<<dim3(LQ / 128, BQ), 256, FUSED_SMEM>>>(
                cur, nxt, cb, ib, Qw, Qb, out);
        }
        uint32_t* tmp = cur; cur = nxt; nxt = tmp;
    }
}